// round 1
// baseline (speedup 1.0000x reference)
#include <cuda_runtime.h>
#include <stdint.h>
#include <math.h>

// Problem constants
#define B_  64
#define D_  128
#define T_  1024
#define K_  2048
#define N_  (B_*T_)          // 65536 points
#define ND_ (N_*D_)          // 8388608 z elements

// Output layout (flat f32 concat, reference return order):
//  [0, 8388608)            z_q transposed back to (B, D, T)
//  [8388608]               commitment loss
//  [8388609]               perplexity
//  [8388610, 8454146)      indices (B, T) as float
#define OUT_ZQ    0
#define OUT_LOSS  8388608
#define OUT_PERP  8388609
#define OUT_IDX   8388610

// Device scratch (no allocations allowed)
__device__ int          g_idx[N_];
__device__ unsigned int g_counts[K_];
__device__ float        g_losspart[B_*D_];   // 8192 partials

// ---------------- packed f32x2 helpers (Blackwell) ----------------
__device__ __forceinline__ void ffma2(unsigned long long &acc,
                                      unsigned long long a,
                                      unsigned long long b) {
    asm("fma.rn.f32x2 %0, %1, %2, %0;" : "+l"(acc) : "l"(a), "l"(b));
}
__device__ __forceinline__ unsigned long long dup2(float x) {
    unsigned long long r;
    asm("mov.b64 %0, {%1, %2};" : "=l"(r) : "f"(x), "f"(x));
    return r;
}
__device__ __forceinline__ float lo32f(unsigned long long u) {
    return __uint_as_float((unsigned)(u & 0xFFFFFFFFull));
}
__device__ __forceinline__ float hi32f(unsigned long long u) {
    return __uint_as_float((unsigned)(u >> 32));
}

// ---------------- kernel 0: zero histogram ----------------
__global__ void vq_init() {
    int i = blockIdx.x * blockDim.x + threadIdx.x;
    if (i < K_) g_counts[i] = 0u;
}

// ---------------- kernel 1: fused GEMM + argmin ----------------
// Block tile: 128 points (BM) x 128 codes (BN), full D=128 in smem.
// 256 threads, each owns an 8x8 micro-tile; FMAs packed 2-wide along codes
// via fma.rn.f32x2. Running per-point argmin kept as packed
// (float_bits<<32)|idx keys in smem, atomicMin for cross-thread combine.
// Tie -> lowest index (matches jnp.argmin), since equal float bits compare
// by the low-32 index.
#define SMEM_K1 (1024 /*best*/ + 4*(128*128 /*Xs*/ + 128*132 /*Es*/ + 128 /*As*/ + 128 /*Cs*/))

__global__ void __launch_bounds__(256, 1)
vq_argmin(const float* __restrict__ z, const float* __restrict__ cb,
          float* __restrict__ out_idx)
{
    extern __shared__ unsigned char sm_raw[];
    unsigned long long* best = (unsigned long long*)sm_raw;          // 128 keys
    float* Xs = (float*)(sm_raw + 1024);                             // [d][m] 128x128
    float* Es = Xs + 128*128;                                        // [d][n] 128x132 (pad 4)
    float* As = Es + 128*132;                                        // ||x||^2 per point
    float* Cs = As + 128;                                            // ||e||^2 per code (tile)

    const int tid  = threadIdx.x;
    const int base = blockIdx.x * 128;          // first point of this tile
    const int b    = base >> 10;                // T=1024 -> tile within one batch row
    const int t0   = base & 1023;

    // Load X tile: Xs[d][m] = z[b, d, t0+m]; rows are contiguous 512B in gmem.
    const float* zp = z + ((size_t)b * D_) * T_ + t0;
    #pragma unroll 4
    for (int f = tid; f < 4096; f += 256) {     // 4096 float4 = 128x128 floats
        int d  = f >> 5;
        int mq = f & 31;
        float4 v = *(const float4*)(zp + (size_t)d * T_ + mq * 4);
        *(float4*)(Xs + d * 128 + mq * 4) = v;
    }
    if (tid < 128) best[tid] = 0xFFFFFFFFFFFFFFFFull;
    __syncthreads();

    // ||x||^2 per point, sequential ascending d, no FMA contraction
    // (mimic reference's square-then-sum rounding).
    if (tid < 128) {
        float s = 0.f;
        for (int d = 0; d < 128; ++d) {
            float x = Xs[d * 128 + tid];
            s = __fadd_rn(s, __fmul_rn(x, x));
        }
        As[tid] = s;
    }

    const int tx = tid & 15, ty = tid >> 4;
    const int m0 = ty * 8, n0 = tx * 8;

    for (int ct = 0; ct < 16; ++ct) {
        __syncthreads();   // previous tile's consumers done with Es/Cs
        // Load + transpose codebook tile: Es[d][c] from cb[ct*128+c][d]
        const float* cbp = cb + (size_t)(ct * 128) * D_;
        #pragma unroll 4
        for (int f = tid; f < 4096; f += 256) {
            int cc = f >> 5;
            int fd = f & 31;
            float4 v = *(const float4*)(cbp + cc * D_ + fd * 4);
            Es[(fd*4+0)*132 + cc] = v.x;
            Es[(fd*4+1)*132 + cc] = v.y;
            Es[(fd*4+2)*132 + cc] = v.z;
            Es[(fd*4+3)*132 + cc] = v.w;
        }
        __syncthreads();

        // ||e||^2 per code in this tile (sequential, no contraction)
        if (tid < 128) {
            float s = 0.f;
            for (int d = 0; d < 128; ++d) {
                float e = Es[d * 132 + tid];
                s = __fadd_rn(s, __fmul_rn(e, e));
            }
            Cs[tid] = s;
        }
        __syncthreads();

        // 8x8 micro-GEMM, codes packed in pairs (f32x2)
        unsigned long long acc[8][4];
        #pragma unroll
        for (int i = 0; i < 8; ++i)
            #pragma unroll
            for (int j = 0; j < 4; ++j) acc[i][j] = 0ull;

        #pragma unroll 4
        for (int d = 0; d < 128; ++d) {
            float4 a0 = *(float4*)(Xs + d * 128 + m0);
            float4 a1 = *(float4*)(Xs + d * 128 + m0 + 4);
            ulonglong2 b0 = *(ulonglong2*)(Es + d * 132 + n0);
            ulonglong2 b1 = *(ulonglong2*)(Es + d * 132 + n0 + 4);
            unsigned long long av[8];
            av[0] = dup2(a0.x); av[1] = dup2(a0.y); av[2] = dup2(a0.z); av[3] = dup2(a0.w);
            av[4] = dup2(a1.x); av[5] = dup2(a1.y); av[6] = dup2(a1.z); av[7] = dup2(a1.w);
            unsigned long long bv[4] = { b0.x, b0.y, b1.x, b1.y };
            #pragma unroll
            for (int i = 0; i < 8; ++i)
                #pragma unroll
                for (int j = 0; j < 4; ++j)
                    ffma2(acc[i][j], av[i], bv[j]);
        }

        // Epilogue: distance = (||x||^2 - 2*dot) + ||e||^2 (reference op order),
        // fold into packed argmin keys.
        #pragma unroll
        for (int i = 0; i < 8; ++i) {
            float A = As[m0 + i];
            unsigned long long bk = 0xFFFFFFFFFFFFFFFFull;
            #pragma unroll
            for (int j = 0; j < 4; ++j) {
                float p0 = lo32f(acc[i][j]);
                float p1 = hi32f(acc[i][j]);
                int   c0 = ct * 128 + n0 + 2 * j;
                float s0 = __fadd_rn(__fadd_rn(A, -2.0f * p0), Cs[n0 + 2*j]);
                float s1 = __fadd_rn(__fadd_rn(A, -2.0f * p1), Cs[n0 + 2*j + 1]);
                unsigned long long k0 =
                    ((unsigned long long)__float_as_uint(s0) << 32) | (unsigned)c0;
                unsigned long long k1 =
                    ((unsigned long long)__float_as_uint(s1) << 32) | (unsigned)(c0 + 1);
                bk = min(bk, min(k0, k1));
            }
            atomicMin(&best[m0 + i], bk);
        }
    }
    __syncthreads();

    if (tid < 128) {
        unsigned long long k = best[tid];
        int idx = (int)(unsigned)(k & 0xFFFFFFFFull);
        int n = base + tid;
        g_idx[n]   = idx;
        out_idx[n] = (float)idx;
        atomicAdd(&g_counts[idx], 1u);
    }
}

// ---------------- kernel 2: z_q scatter + loss partials ----------------
// One block per (b, d) pair; t contiguous -> coalesced z read and out write;
// codebook gather is L2-resident (1 MB).
__global__ void __launch_bounds__(256)
vq_write(const float* __restrict__ z, const float* __restrict__ cb,
         float* __restrict__ out)
{
    int bd = blockIdx.x;             // b*128 + d
    int b  = bd >> 7;
    int d  = bd & 127;
    size_t base = (size_t)bd << 10;  // linear offset of out[b][d][0]
    float lsum = 0.f;
    #pragma unroll
    for (int k = 0; k < 4; ++k) {
        int t = threadIdx.x + k * 256;
        int n = (b << 10) + t;
        int idx = g_idx[n];
        float q  = cb[(size_t)idx * D_ + d];
        float zv = z[base + t];
        out[base + t] = q;           // straight-through forward == z_q
        float df = zv - q;
        lsum += df * df;
    }
    __shared__ float red[256];
    red[threadIdx.x] = lsum;
    __syncthreads();
    #pragma unroll
    for (int s = 128; s > 0; s >>= 1) {
        if (threadIdx.x < s) red[threadIdx.x] += red[threadIdx.x + s];
        __syncthreads();
    }
    if (threadIdx.x == 0) g_losspart[bd] = red[0];
}

// ---------------- kernel 3: scalars (deterministic reductions) ----------------
__global__ void __launch_bounds__(256)
vq_finalize(float* __restrict__ out)
{
    __shared__ double red[256];
    int tid = threadIdx.x;

    // commitment loss
    double s = 0.0;
    for (int i = tid; i < B_*D_; i += 256) s += (double)g_losspart[i];
    red[tid] = s;
    __syncthreads();
    #pragma unroll
    for (int k = 128; k > 0; k >>= 1) {
        if (tid < k) red[tid] += red[tid + k];
        __syncthreads();
    }
    double loss = 0.25 * red[0] / (double)ND_;
    __syncthreads();

    // perplexity
    double h = 0.0;
    for (int i = tid; i < K_; i += 256) {
        double p = (double)g_counts[i] / (double)N_;
        h += p * log(p + 1e-10);
    }
    red[tid] = h;
    __syncthreads();
    #pragma unroll
    for (int k = 128; k > 0; k >>= 1) {
        if (tid < k) red[tid] += red[tid + k];
        __syncthreads();
    }
    if (tid == 0) {
        out[OUT_LOSS] = (float)loss;
        out[OUT_PERP] = (float)exp(-red[0]);
    }
}

// ---------------- launch ----------------
extern "C" void kernel_launch(void* const* d_in, const int* in_sizes, int n_in,
                              void* d_out, int out_size)
{
    const float* z  = (const float*)d_in[0];   // (B, D, T) f32
    const float* cb = (const float*)d_in[1];   // (K, D)    f32
    float* out = (float*)d_out;

    cudaFuncSetAttribute(vq_argmin,
                         cudaFuncAttributeMaxDynamicSharedMemorySize, SMEM_K1);

    vq_init<<<8, 256>>>();
    vq_argmin<<<N_/128, 256, SMEM_K1>>>(z, cb, out + OUT_IDX);
    vq_write<<<B_*D_, 256>>>(z, cb, out + OUT_ZQ);
    vq_finalize<<<1, 256>>>(out);
}

// round 7
// speedup vs baseline: 2.3966x; 2.3966x over previous
#include <cuda_runtime.h>
#include <stdint.h>
#include <math.h>

// Problem constants
#define B_  64
#define D_  128
#define T_  1024
#define K_  2048
#define N_  (B_*T_)          // 65536 points
#define ND_ (N_*D_)          // 8388608

// Output layout (flat f32 concat): zq | loss | perp | indices
#define OUT_ZQ    0
#define OUT_LOSS  8388608
#define OUT_PERP  8388609
#define OUT_IDX   8388610

// flag margin on approx keys (covers 2x half-ulp(128)=1.5e-5 + 14 sigma tf32 noise)
#define MARGIN_F  6e-5f

// ---- device scratch ----
__device__ unsigned int       g_counts[K_];
__device__ float              g_call[K_];     // ||e||^2 + 1 (approx bias)
__device__ float              g_cexact[K_];   // ||e||^2 exact sequential
__device__ float              g_losspart[8192];
__device__ int                g_bestidx[N_];
__device__ int                g_flagarr[N_];
__device__ int                g_plist[N_];
__device__ unsigned long long g_exactkey[N_];
__device__ unsigned int       g_nflag;
__device__ unsigned int       g_done;

// =====================================================================
// SMEM layout for vq_main
// =====================================================================
#define XS_OFF     0                        // u32[128*132] tf32 X, [m][k]
#define CALL_OFF   (XS_OFF + 128*132*4)     // float[2048]
#define PAIR_OFF   (CALL_OFF + 2048*4)      // u64[128][4][2]
#define BBUF_OFF   (PAIR_OFF + 128*4*2*8)   // 2 x u32[128*132]
#define BBUF_SZ    (128*132*4)              // 67584
#define SMEM_K1    (BBUF_OFF + 2*BBUF_SZ)   // 219136

// SMEM layout for vq_recheck
#define RC_XR      0                        // float[128][132]
#define RC_ER      (128*132*4)              // float[128][132]
#define RC_AS      (2*128*132*4)            // float[128]
#define RC_CX      (RC_AS + 512)            // float[128]
#define SMEM_RC    (RC_CX + 512)            // 136192

// =====================================================================
// PTX helpers (baseline sm_80+ features only)
// =====================================================================
__device__ __forceinline__ uint32_t smem_u32(const void* p) {
    uint32_t a;
    asm("{ .reg .u64 t; cvta.to.shared.u64 t, %1; cvt.u32.u64 %0, t; }"
        : "=r"(a) : "l"(p));
    return a;
}
__device__ __forceinline__ void cp_async16(uint32_t dst, const void* src) {
    asm volatile("cp.async.ca.shared.global [%0], [%1], 16;"
                 :: "r"(dst), "l"(src) : "memory");
}
#define CP_COMMIT() asm volatile("cp.async.commit_group;" ::: "memory")
#define CP_WAIT(n)  asm volatile("cp.async.wait_group %0;" :: "n"(n) : "memory")

__device__ __forceinline__ uint32_t f2tf32(float x) {
    uint32_t u;
    asm("cvt.rna.tf32.f32 %0, %1;" : "=r"(u) : "f"(x));
    return u;
}
__device__ __forceinline__ void mma_tf32(float* c,
                                         uint32_t a0, uint32_t a1,
                                         uint32_t a2, uint32_t a3,
                                         uint32_t b0, uint32_t b1) {
    asm volatile(
        "mma.sync.aligned.m16n8k8.row.col.f32.tf32.tf32.f32 "
        "{%0,%1,%2,%3}, {%4,%5,%6,%7}, {%8,%9}, {%0,%1,%2,%3};"
        : "+f"(c[0]), "+f"(c[1]), "+f"(c[2]), "+f"(c[3])
        : "r"(a0), "r"(a1), "r"(a2), "r"(a3), "r"(b0), "r"(b1));
}

// track two smallest packed keys
__device__ __forceinline__ void upd2(unsigned long long &b1,
                                     unsigned long long &b2,
                                     float d, int code) {
    unsigned long long k =
        ((unsigned long long)__float_as_uint(d) << 32) | (unsigned)code;
    if (k < b1) { b2 = b1; b1 = k; }
    else if (k < b2) { b2 = k; }
}
// merge two sorted pairs -> two smallest of union
__device__ __forceinline__ void merge_pair(unsigned long long &a1,
                                           unsigned long long &a2,
                                           unsigned long long c1,
                                           unsigned long long c2) {
    unsigned long long m1 = a1 < c1 ? a1 : c1;
    unsigned long long mx = a1 < c1 ? c1 : a1;
    unsigned long long m2 = a2 < c2 ? a2 : c2;
    a1 = m1;
    a2 = mx < m2 ? mx : m2;
}

// =====================================================================
// kernel 1: codebook norms + resets
// =====================================================================
__global__ void vq_pre(const float* __restrict__ cb) {
    int c = blockIdx.x * 256 + threadIdx.x;
    if (c < K_) {
        const float4* r = (const float4*)(cb + (size_t)c * D_);
        float s = 0.0f;
        #pragma unroll 8
        for (int q = 0; q < 32; ++q) {
            float4 v = r[q];
            s = __fadd_rn(s, __fmul_rn(v.x, v.x));
            s = __fadd_rn(s, __fmul_rn(v.y, v.y));
            s = __fadd_rn(s, __fmul_rn(v.z, v.z));
            s = __fadd_rn(s, __fmul_rn(v.w, v.w));
        }
        g_cexact[c] = s;
        g_call[c]   = s + 1.0f;
        g_counts[c] = 0u;
        if (c == 0) { g_nflag = 0u; g_done = 0u; }
    }
}

// =====================================================================
// kernel 2: tf32 mma.sync GEMM + best/2nd-best argmin + flag compaction
// 512 CTAs x 256 threads (2 m-warps x 4 n-warps, warp 64x32)
// =====================================================================
__global__ void __launch_bounds__(256, 1)
vq_main(const float* __restrict__ z, const float* __restrict__ cb)
{
    extern __shared__ char sm[];
    uint32_t* Xs  = (uint32_t*)(sm + XS_OFF);
    float* CallS  = (float*)(sm + CALL_OFF);
    unsigned long long (*pairs)[4][2] =
        (unsigned long long(*)[4][2])(sm + PAIR_OFF);
    const uint32_t smb = smem_u32(sm);

    const int tid  = threadIdx.x;
    const int wid  = tid >> 5;
    const int lane = tid & 31;
    const int quad = lane >> 2;
    const int tq   = lane & 3;
    const int wm   = wid & 1;
    const int wn   = wid >> 1;

    const int base = blockIdx.x * 128;
    const int b    = base >> 10;
    const int t0   = base & 1023;

    // ---- stage z tile [k][m] into B-buffer region ----
    float* Ss = (float*)(sm + BBUF_OFF);
    const float* zp = z + (size_t)b * D_ * T_ + t0;
    #pragma unroll 4
    for (int f = tid; f < 4096; f += 256) {
        int d = f >> 5, mq = f & 31;
        *(float4*)(Ss + d * 128 + mq * 4) = *(const float4*)(zp + (size_t)d * T_ + mq * 4);
    }
    #pragma unroll
    for (int j = 0; j < 8; ++j) CallS[tid + 256 * j] = g_call[tid + 256 * j];
    __syncthreads();

    // ---- transpose to Xs[m][k] (tf32, stride 132) ----
    {
        int m = tid & 127, kh = tid >> 7;
        #pragma unroll 4
        for (int j = 0; j < 64; ++j) {
            float x = Ss[(kh * 64 + j) * 128 + m];
            Xs[m * 132 + kh * 64 + j] = f2tf32(x);
        }
    }
    __syncthreads();   // Ss dead

    auto issueB = [&](int s, int buf) {
        uint32_t dst0 = smb + BBUF_OFF + (uint32_t)buf * BBUF_SZ;
        const float* src0 = cb + (size_t)s * 128 * D_;
        #pragma unroll
        for (int j = 0; j < 16; ++j) {
            int f = tid + 256 * j;
            int n = f >> 5, q = f & 31;
            cp_async16(dst0 + (uint32_t)(n * 132 + q * 4) * 4,
                       src0 + (size_t)n * D_ + q * 4);
        }
        CP_COMMIT();
    };
    issueB(0, 0);

    unsigned long long b1[4][2], b2[4][2];
    #pragma unroll
    for (int mi = 0; mi < 4; ++mi) {
        b1[mi][0] = b1[mi][1] = 0xFFFFFFFFFFFFFFFFull;
        b2[mi][0] = b2[mi][1] = 0xFFFFFFFFFFFFFFFFull;
    }

    const uint32_t* Ab = Xs + (wm * 64 + quad) * 132 + tq;

    for (int s = 0; s < 16; ++s) {
        if (s + 1 < 16) issueB(s + 1, (s + 1) & 1);
        if (s + 1 < 16) { CP_WAIT(1); } else { CP_WAIT(0); }
        __syncthreads();

        const uint32_t* Bb = (const uint32_t*)(sm + BBUF_OFF + (s & 1) * BBUF_SZ)
                             + (wn * 32 + quad) * 132 + tq;

        float acc[4][4][4];
        #pragma unroll
        for (int mi = 0; mi < 4; ++mi)
            #pragma unroll
            for (int ni = 0; ni < 4; ++ni)
                #pragma unroll
                for (int r = 0; r < 4; ++r) acc[mi][ni][r] = 0.0f;

        #pragma unroll
        for (int k8 = 0; k8 < 16; ++k8) {
            const int k = k8 * 8;
            uint32_t a[4][4];
            #pragma unroll
            for (int mi = 0; mi < 4; ++mi) {
                const uint32_t* ap = Ab + mi * (16 * 132) + k;
                a[mi][0] = ap[0];
                a[mi][1] = ap[8 * 132];
                a[mi][2] = ap[4];
                a[mi][3] = ap[8 * 132 + 4];
            }
            uint32_t bb[4][2];
            #pragma unroll
            for (int ni = 0; ni < 4; ++ni) {
                const uint32_t* bp = Bb + ni * (8 * 132) + k;
                bb[ni][0] = bp[0];
                bb[ni][1] = bp[4];
            }
            #pragma unroll
            for (int mi = 0; mi < 4; ++mi)
                #pragma unroll
                for (int ni = 0; ni < 4; ++ni)
                    mma_tf32(acc[mi][ni], a[mi][0], a[mi][1], a[mi][2], a[mi][3],
                             bb[ni][0], bb[ni][1]);
        }

        #pragma unroll
        for (int ni = 0; ni < 4; ++ni) {
            int nb = s * 128 + wn * 32 + ni * 8 + 2 * tq;
            float c0 = CallS[nb], c1 = CallS[nb + 1];
            #pragma unroll
            for (int mi = 0; mi < 4; ++mi) {
                upd2(b1[mi][0], b2[mi][0], fmaf(acc[mi][ni][0], -2.0f, c0), nb);
                upd2(b1[mi][0], b2[mi][0], fmaf(acc[mi][ni][1], -2.0f, c1), nb + 1);
                upd2(b1[mi][1], b2[mi][1], fmaf(acc[mi][ni][2], -2.0f, c0), nb);
                upd2(b1[mi][1], b2[mi][1], fmaf(acc[mi][ni][3], -2.0f, c1), nb + 1);
            }
        }
        __syncthreads();
    }

    // ---- cross-thread (tq group) reduce of (best, second) ----
    #pragma unroll
    for (int mi = 0; mi < 4; ++mi)
        #pragma unroll
        for (int h = 0; h < 2; ++h) {
            unsigned long long a1 = b1[mi][h], a2 = b2[mi][h];
            #pragma unroll
            for (int o = 1; o <= 2; o <<= 1) {
                unsigned long long c1 = __shfl_xor_sync(0xFFFFFFFFu, a1, o);
                unsigned long long c2 = __shfl_xor_sync(0xFFFFFFFFu, a2, o);
                merge_pair(a1, a2, c1, c2);
            }
            if (tq == 0) {
                int row = wm * 64 + mi * 16 + h * 8 + quad;
                pairs[row][wn][0] = a1;
                pairs[row][wn][1] = a2;
            }
        }
    __syncthreads();

    if (tid < 128) {
        unsigned long long a1 = pairs[tid][0][0], a2 = pairs[tid][0][1];
        #pragma unroll
        for (int wq = 1; wq < 4; ++wq)
            merge_pair(a1, a2, pairs[tid][wq][0], pairs[tid][wq][1]);
        int n   = base + tid;
        int idx = (int)(unsigned)a1;
        float d1 = __uint_as_float((unsigned)(a1 >> 32));
        float d2 = __uint_as_float((unsigned)(a2 >> 32));
        g_bestidx[n] = idx;
        int fl = (d2 - d1 < MARGIN_F) ? 1 : 0;
        g_flagarr[n] = fl;
        if (fl) {
            unsigned slot = atomicAdd(&g_nflag, 1u);
            g_plist[slot] = n;
            g_exactkey[n] = 0xFFFFFFFFFFFFFFFFull;
        }
    }
}

// =====================================================================
// kernel 3: exact fp32 recheck of flagged points (round-1 arithmetic)
// =====================================================================
__global__ void __launch_bounds__(256, 1)
vq_recheck(const float* __restrict__ z, const float* __restrict__ cb)
{
    extern __shared__ char sm[];
    float* Xr = (float*)(sm + RC_XR);   // [128][132]
    float* Er = (float*)(sm + RC_ER);   // [128][132]
    float* As = (float*)(sm + RC_AS);
    float* Cx = (float*)(sm + RC_CX);
    const int tid = threadIdx.x;

    const unsigned nflag = g_nflag;
    if (nflag == 0) return;
    const int ptiles = (int)((nflag + 127) >> 7);
    const int items  = ptiles * 16;

    for (int item = blockIdx.x; item < items; item += gridDim.x) {
        const int pt = item >> 4, ct = item & 15;
        __syncthreads();
        // stage codebook tile + exact norms
        {
            const float* src = cb + (size_t)ct * 128 * D_;
            #pragma unroll 4
            for (int f = tid; f < 4096; f += 256) {
                int c = f >> 5, q = f & 31;
                *(float4*)(Er + c * 132 + q * 4) = *(const float4*)(src + (size_t)c * D_ + q * 4);
            }
            if (tid < 128) Cx[tid] = g_cexact[ct * 128 + tid];
        }
        // stage flagged x rows from z (L2-resident)
        for (int f = tid; f < 16384; f += 256) {
            int p = f >> 7, d = f & 127;
            int slot = pt * 128 + p;
            int n = (slot < (int)nflag) ? g_plist[slot] : g_plist[0];
            Xr[p * 132 + d] = z[((size_t)(n >> 10) * 128 + d) * 1024 + (n & 1023)];
        }
        __syncthreads();
        if (tid < 128) {
            float s = 0.0f;
            for (int d = 0; d < 128; ++d) {
                float x = Xr[tid * 132 + d];
                s = __fadd_rn(s, __fmul_rn(x, x));
            }
            As[tid] = s;
        }
        __syncthreads();

        const int w = tid >> 5, lane = tid & 31;
        const int p  = (w & 3) * 32 + lane;
        const int c0 = (w >> 2) * 64;
        float acc[64];
        #pragma unroll 16
        for (int j = 0; j < 64; ++j) acc[j] = 0.0f;

        #pragma unroll 1
        for (int dq = 0; dq < 32; ++dq) {
            float4 x4 = *(const float4*)(Xr + p * 132 + dq * 4);
            #pragma unroll 8
            for (int j = 0; j < 64; ++j) {
                float4 e4 = *(const float4*)(Er + (c0 + j) * 132 + dq * 4);
                acc[j] = __fmaf_rn(x4.x, e4.x, acc[j]);
                acc[j] = __fmaf_rn(x4.y, e4.y, acc[j]);
                acc[j] = __fmaf_rn(x4.z, e4.z, acc[j]);
                acc[j] = __fmaf_rn(x4.w, e4.w, acc[j]);
            }
        }

        float A = As[p];
        unsigned long long bk = 0xFFFFFFFFFFFFFFFFull;
        #pragma unroll 16
        for (int j = 0; j < 64; ++j) {
            float s = __fadd_rn(__fadd_rn(A, -2.0f * acc[j]), Cx[c0 + j]);
            int code = ct * 128 + c0 + j;
            unsigned long long k =
                ((unsigned long long)__float_as_uint(s) << 32) | (unsigned)code;
            bk = bk < k ? bk : k;
        }
        int slot = pt * 128 + p;
        if (slot < (int)nflag)
            atomicMin(&g_exactkey[g_plist[slot]], bk);
    }
}

// =====================================================================
// kernel 4: z_q + indices + histogram + loss; last block does scalars
// =====================================================================
__global__ void __launch_bounds__(256)
vq_postfin(const float* __restrict__ z, const float* __restrict__ cb,
           float* __restrict__ out)
{
    __shared__ float red[256];
    __shared__ int islast;
    const int tid = threadIdx.x;
    const int bd  = blockIdx.x;
    const int b   = bd >> 7, d = bd & 127;

    float ls = 0.0f;
    #pragma unroll
    for (int k = 0; k < 4; ++k) {
        int t = tid + k * 256;
        int n = (b << 10) + t;
        int idx = g_flagarr[n] ? (int)(unsigned)g_exactkey[n] : g_bestidx[n];
        float q  = cb[(size_t)idx * D_ + d];
        float zv = z[(size_t)bd * 1024 + t];
        out[OUT_ZQ + (size_t)bd * 1024 + t] = q;
        float df = zv - q;
        ls += df * df;
        if (d == 0) {
            out[OUT_IDX + n] = (float)idx;
            atomicAdd(&g_counts[idx], 1u);
        }
    }
    red[tid] = ls;
    __syncthreads();
    #pragma unroll
    for (int s = 128; s > 0; s >>= 1) {
        if (tid < s) red[tid] += red[tid + s];
        __syncthreads();
    }
    if (tid == 0) {
        g_losspart[bd] = red[0];
        __threadfence();
        unsigned old = atomicAdd(&g_done, 1u);
        islast = (old == gridDim.x - 1) ? 1 : 0;
    }
    __syncthreads();
    if (!islast) return;
    __threadfence();

    float s = 0.0f;
    for (int i = tid; i < 8192; i += 256) s += g_losspart[i];
    red[tid] = s;
    __syncthreads();
    #pragma unroll
    for (int k2 = 128; k2 > 0; k2 >>= 1) {
        if (tid < k2) red[tid] += red[tid + k2];
        __syncthreads();
    }
    float loss = 0.25f * red[0] / (float)ND_;
    __syncthreads();

    float h = 0.0f;
    for (int i = tid; i < K_; i += 256) {
        float p = (float)g_counts[i] / (float)N_;
        h += p * logf(p + 1e-10f);
    }
    red[tid] = h;
    __syncthreads();
    #pragma unroll
    for (int k2 = 128; k2 > 0; k2 >>= 1) {
        if (tid < k2) red[tid] += red[tid + k2];
        __syncthreads();
    }
    if (tid == 0) {
        out[OUT_LOSS] = loss;
        out[OUT_PERP] = expf(-red[0]);
    }
}

// =====================================================================
// launch: exactly 4 kernels/call so ncu (-s 5 -c 1) lands on vq_main
// =====================================================================
extern "C" void kernel_launch(void* const* d_in, const int* in_sizes, int n_in,
                              void* d_out, int out_size)
{
    const float* z  = (const float*)d_in[0];   // (B, D, T)
    const float* cb = (const float*)d_in[1];   // (K, D)
    float* out = (float*)d_out;

    cudaFuncSetAttribute(vq_main,
                         cudaFuncAttributeMaxDynamicSharedMemorySize, SMEM_K1);
    cudaFuncSetAttribute(vq_recheck,
                         cudaFuncAttributeMaxDynamicSharedMemorySize, SMEM_RC);

    vq_pre<<<8, 256>>>(cb);
    vq_main<<<N_/128, 256, SMEM_K1>>>(z, cb);
    vq_recheck<<<2048, 256, SMEM_RC>>>(z, cb);
    vq_postfin<<<8192, 256>>>(z, cb, out);
}